// round 12
// baseline (speedup 1.0000x reference)
#include <cuda_runtime.h>
#include <cuda_fp16.h>
#include <cstdint>
#include <cstddef>

#define IN_F   1024
#define OUT_F  1024
#define BATCH  8192
#define NFEAT  7
#define KTOT   (IN_F * NFEAT)   // 7168

// ---------------------------------------------------------------------------
// Scratch: fp16 combined weights [o][k]. (A is synthesized in-smem from x.)
// ---------------------------------------------------------------------------
__device__ __align__(256) __half g_W[(size_t)OUT_F * KTOT];

// ---------------------------------------------------------------------------
// Helpers
// ---------------------------------------------------------------------------
__device__ __forceinline__ unsigned smem_u32(const void* p) {
    return (unsigned)__cvta_generic_to_shared(p);
}
#define CP_ASYNC16(dst_u32, src_ptr) \
    asm volatile("cp.async.cg.shared.global [%0], [%1], 16;\n" :: "r"(dst_u32), "l"(src_ptr))
#define CP_COMMIT() asm volatile("cp.async.commit_group;\n")
#define CP_WAIT(n)  asm volatile("cp.async.wait_group %0;\n" :: "n"(n))

#define LDSM_X4(r0, r1, r2, r3, addr) \
    asm volatile("ldmatrix.sync.aligned.m8n8.x4.shared.b16 {%0,%1,%2,%3}, [%4];" \
                 : "=r"(r0), "=r"(r1), "=r"(r2), "=r"(r3) : "r"(addr))

#define MMA_F16(d, a0, a1, a2, a3, b0, b1) \
    asm volatile( \
        "mma.sync.aligned.m16n8k16.row.col.f32.f16.f16.f32 " \
        "{%0,%1,%2,%3}, {%4,%5,%6,%7}, {%8,%9}, {%0,%1,%2,%3};" \
        : "+f"((d)[0]), "+f"((d)[1]), "+f"((d)[2]), "+f"((d)[3]) \
        : "r"(a0), "r"(a1), "r"(a2), "r"(a3), "r"(b0), "r"(b1))

#define STS16(addr, h) \
    asm volatile("st.shared.b16 [%0], %1;" :: "r"(addr), "h"(h) : "memory")

// ---------------------------------------------------------------------------
// Kernel 1: combined weights -> fp16, layout [o][k]
// ---------------------------------------------------------------------------
__global__ void kan_prep_w(const float* __restrict__ bw,
                           const float* __restrict__ sw,
                           const float* __restrict__ sc) {
    __shared__ __half sbuf[256 * NFEAT];
    int o = blockIdx.x;
    int tid = threadIdx.x;
    int i = blockIdx.y * 256 + tid;
    size_t oi = (size_t)o * IN_F + i;
    float s = sc[oi];
    float vals[NFEAT];
    vals[0] = bw[oi];
    const float* swp = sw + oi * 6;
#pragma unroll
    for (int n = 0; n < 6; n++) vals[n + 1] = swp[n] * s;
#pragma unroll
    for (int j = 0; j < NFEAT; j++)
        sbuf[tid * NFEAT + j] = __float2half_rn(vals[j]);
    __syncthreads();
    float4* dst = (float4*)(g_W + (size_t)o * KTOT + (size_t)blockIdx.y * (256 * NFEAT));
    if (tid < 224) dst[tid] = ((const float4*)sbuf)[tid];
}

// ---------------------------------------------------------------------------
// Device feature math: silu (MUFU-free poly) + closed-form uniform cubic
// B-spline. Returns the 7 per-input features.
// ---------------------------------------------------------------------------
__device__ __forceinline__ void kan_feat(float xv, float vals[NFEAT]) {
    float tt = xv * xv;
    float P = fmaf(tt, fmaf(tt, fmaf(tt, -2.10813e-4f, 2.08333333e-3f),
                            -2.08333333e-2f), 0.25f);
    float sil = xv * fmaf(xv, P, 0.5f);

    float u  = (xv + 1.0f) * 1.5f;
    int idx  = (int)floorf(u);
    idx = idx < 0 ? 0 : (idx > 2 ? 2 : idx);
    float t  = u - (float)idx;
    float t2 = t * t, t3 = t2 * t;
    float omt = 1.0f - t;
    const float c6 = 1.0f / 6.0f;
    float v0 = omt * omt * omt * c6;
    float v1 = (3.0f * t3 - 6.0f * t2 + 4.0f) * c6;
    float v2 = (-3.0f * t3 + 3.0f * t2 + 3.0f * t + 1.0f) * c6;
    float v3 = t3 * c6;

    vals[0] = sil;
    vals[1] = (idx == 0) ? v0 : 0.0f;
    vals[2] = (idx == 0) ? v1 : ((idx == 1) ? v0 : 0.0f);
    vals[3] = (idx == 0) ? v2 : ((idx == 1) ? v1 : v0);
    vals[4] = (idx == 0) ? v3 : ((idx == 1) ? v2 : v1);
    vals[5] = (idx == 1) ? v3 : ((idx == 2) ? v2 : 0.0f);
    vals[6] = (idx == 2) ? v3 : 0.0f;
}

// ---------------------------------------------------------------------------
// Kernel 2: fused GEMM.  C[b,o] = sum_k feat(x)[b][k] * W[o][k]
// CTA 128x256, BK=64 halves, 144B smem row stride (conflict-free LDSM),
// 8 warps (warp tile 64x64), 3-stage ring. B via cp.async; A synthesized
// in-smem from x by the producer path (hidden under the MMA shadow).
// K window [64t, 64t+64) is covered exactly by x columns i0..i0+9 (63 = 7*9).
// ---------------------------------------------------------------------------
#define BM 128
#define BN 256
#define BK 64
#define NT (KTOT / BK)          // 112
#define ROWB 144                // bytes per smem row (128 data + 16 pad)
#define A_STG_B (BM * ROWB)     // 18432
#define B_STG_B (BN * ROWB)     // 36864
#define STG_B (A_STG_B + B_STG_B)
#define NSTAGE 3
#define SMEM_TOTAL (NSTAGE * STG_B)   // 165888

// Producer: fill stage buffer (A from x, B via cp.async), commit 1 group.
__device__ __forceinline__ void load_stage(uint32_t sb, const float* __restrict__ x,
                                           int bm0, int bn0, int t, int stg,
                                           int tid) {
    uint32_t base = sb + stg * STG_B;
    const int k0 = t * BK;
    const int i0 = k0 / NFEAT;

    // A: 128 rows x 10 x-columns -> 1280 items, 5 per thread
#pragma unroll
    for (int r = 0; r < 5; r++) {
        int item = tid + r * 256;
        int row = item / 10, ii = item % 10;
        int i = i0 + ii;                       // i0+9 <= 1023 always
        float xv = __ldg(x + (size_t)(bm0 + row) * IN_F + i);
        float vals[NFEAT];
        kan_feat(xv, vals);
        int kb = i * NFEAT - k0;               // window-relative k of vals[0]
        uint32_t rbase = base + (uint32_t)(row * ROWB);
#pragma unroll
        for (int j = 0; j < NFEAT; j++) {
            int kk = kb + j;
            if (kk >= 0 && kk < BK) {
                __half h = __float2half_rn(vals[j]);
                STS16(rbase + (uint32_t)(kk * 2), __half_as_ushort(h));
            }
        }
    }

    // B: 256 rows x 8 chunks of 16B
    uint32_t bbase = base + A_STG_B;
#pragma unroll
    for (int r = 0; r < 8; r++) {
        int c = tid + r * 256;
        int row = c >> 3, ch = c & 7;
        CP_ASYNC16(bbase + (uint32_t)(row * ROWB + ch * 16),
                   g_W + (size_t)(bn0 + row) * KTOT + k0 + ch * 8);
    }
    CP_COMMIT();
}

struct Frag {
    uint32_t a[4][4];
    uint32_t b[8][2];
};

__device__ __forceinline__ void load_frag(Frag& f, uint32_t abase, uint32_t bbase,
                                          int kk) {
    const uint32_t ko = (uint32_t)(kk * 32);
#pragma unroll
    for (int mb = 0; mb < 4; mb++)
        LDSM_X4(f.a[mb][0], f.a[mb][1], f.a[mb][2], f.a[mb][3],
                abase + (uint32_t)(mb * 16 * ROWB) + ko);
#pragma unroll
    for (int n2 = 0; n2 < 4; n2++)
        LDSM_X4(f.b[2 * n2][0], f.b[2 * n2][1], f.b[2 * n2 + 1][0], f.b[2 * n2 + 1][1],
                bbase + (uint32_t)(n2 * 16 * ROWB) + ko);
}

__global__ __launch_bounds__(256, 1) void kan_gemm(const float* __restrict__ x,
                                                   float* __restrict__ C) {
    extern __shared__ char dsm[];
    uint32_t sb = smem_u32(dsm);
    const int tid = threadIdx.x;
    const int wid = tid >> 5, lane = tid & 31;
    const int q = lane >> 2, cl = lane & 3;
    const int bm0 = blockIdx.y * BM;   // y = bm (slow)
    const int bn0 = blockIdx.x * BN;   // x = bn (fast): consecutive CTAs share A/x
    const int m0 = (wid & 1) * 64;
    const int n0 = (wid >> 1) * 64;

    float d[4][8][4];
#pragma unroll
    for (int mb = 0; mb < 4; mb++)
#pragma unroll
        for (int nb = 0; nb < 8; nb++)
#pragma unroll
            for (int r = 0; r < 4; r++) d[mb][nb][r] = 0.0f;

    load_stage(sb, x, bm0, bn0, 0, 0, tid);
    load_stage(sb, x, bm0, bn0, 1, 1, tid);

    const int r8 = lane & 7, tq = lane >> 3;
    const uint32_t afoff =
        (uint32_t)((m0 + (tq & 1) * 8 + r8) * ROWB + (tq >> 1) * 16);
    const uint32_t bfoff =
        (uint32_t)(A_STG_B + (n0 + (tq >> 1) * 8 + r8) * ROWB + (tq & 1) * 16);

    Frag fr[2];
    for (int t = 0; t < NT; t++) {
        const int stg = t % NSTAGE;
        CP_WAIT(1);
        __syncthreads();   // orders stage-(t) reads after its fill (STS + cp.async)
        if (t + 2 < NT) load_stage(sb, x, bm0, bn0, t + 2, (t + 2) % NSTAGE, tid);

        const uint32_t stbase = sb + stg * STG_B;
        const uint32_t abase = stbase + afoff;
        const uint32_t bbase = stbase + bfoff;

        load_frag(fr[0], abase, bbase, 0);
#pragma unroll
        for (int kk = 0; kk < 4; kk++) {
            if (kk < 3) load_frag(fr[(kk + 1) & 1], abase, bbase, kk + 1);
            Frag& f = fr[kk & 1];
#pragma unroll
            for (int mb = 0; mb < 4; mb++)
#pragma unroll
                for (int nb = 0; nb < 8; nb++)
                    MMA_F16(d[mb][nb], f.a[mb][0], f.a[mb][1], f.a[mb][2], f.a[mb][3],
                            f.b[nb][0], f.b[nb][1]);
        }
    }

#pragma unroll
    for (int mb = 0; mb < 4; mb++) {
        int row0 = bm0 + m0 + mb * 16 + q;
#pragma unroll
        for (int nb = 0; nb < 8; nb++) {
            int col = bn0 + n0 + nb * 8 + 2 * cl;
            float2* p0 = (float2*)(C + (size_t)row0 * OUT_F + col);
            *p0 = make_float2(d[mb][nb][0], d[mb][nb][1]);
            float2* p1 = (float2*)(C + (size_t)(row0 + 8) * OUT_F + col);
            *p1 = make_float2(d[mb][nb][2], d[mb][nb][3]);
        }
    }
}

// ---------------------------------------------------------------------------
// Launch. Inputs: x, base_weight, spline_weight, spline_scaler, grid
// ---------------------------------------------------------------------------
extern "C" void kernel_launch(void* const* d_in, const int* in_sizes, int n_in,
                              void* d_out, int out_size) {
    (void)in_sizes; (void)n_in; (void)out_size;
    const float* x  = (const float*)d_in[0];
    const float* bw = (const float*)d_in[1];
    const float* sw = (const float*)d_in[2];
    const float* sc = (const float*)d_in[3];
    float* out = (float*)d_out;

    cudaFuncSetAttribute(kan_gemm, cudaFuncAttributeMaxDynamicSharedMemorySize,
                         SMEM_TOTAL);

    kan_prep_w<<<dim3(OUT_F, IN_F / 256), 256>>>(bw, sw, sc);
    kan_gemm<<<dim3(OUT_F / BN, BATCH / BM), 256, SMEM_TOTAL>>>(x, out);
}

// round 13
// speedup vs baseline: 1.3402x; 1.3402x over previous
#include <cuda_runtime.h>
#include <cuda_fp16.h>
#include <cstdint>
#include <cstddef>

#define IN_F   1024
#define OUT_F  1024
#define BATCH  8192
#define NFEAT  7
#define KTOT   (IN_F * NFEAT)   // 7168

// ---------------------------------------------------------------------------
// Scratch: fp16 operands. g_A: [b][k] row-major. g_W: [o][k].
// ---------------------------------------------------------------------------
__device__ __align__(256) __half g_A[(size_t)BATCH * KTOT];
__device__ __align__(256) __half g_W[(size_t)OUT_F * KTOT];

// ---------------------------------------------------------------------------
// Helpers
// ---------------------------------------------------------------------------
__device__ __forceinline__ unsigned smem_u32(const void* p) {
    return (unsigned)__cvta_generic_to_shared(p);
}
#define CP_ASYNC16(dst_u32, src_ptr) \
    asm volatile("cp.async.cg.shared.global [%0], [%1], 16;\n" :: "r"(dst_u32), "l"(src_ptr))
#define CP_COMMIT() asm volatile("cp.async.commit_group;\n")
#define CP_WAIT(n)  asm volatile("cp.async.wait_group %0;\n" :: "n"(n))

#define LDSM_X4(r0, r1, r2, r3, addr) \
    asm volatile("ldmatrix.sync.aligned.m8n8.x4.shared.b16 {%0,%1,%2,%3}, [%4];" \
                 : "=r"(r0), "=r"(r1), "=r"(r2), "=r"(r3) : "r"(addr))

#define MMA_F16(d, a0, a1, a2, a3, b0, b1) \
    asm volatile( \
        "mma.sync.aligned.m16n8k16.row.col.f32.f16.f16.f32 " \
        "{%0,%1,%2,%3}, {%4,%5,%6,%7}, {%8,%9}, {%0,%1,%2,%3};" \
        : "+f"((d)[0]), "+f"((d)[1]), "+f"((d)[2]), "+f"((d)[3]) \
        : "r"(a0), "r"(a1), "r"(a2), "r"(a3), "r"(b0), "r"(b1))

// ---------------------------------------------------------------------------
// Kernel 1: combined prep (one launch, two independent grid partitions).
//   blockIdx.x <  BATCH : features for batch row bx -> g_A
//   blockIdx.x >= BATCH : combined weights for out row bx-BATCH -> g_W
// ---------------------------------------------------------------------------
__global__ void kan_prep(const float* __restrict__ x,
                         const float* __restrict__ bw,
                         const float* __restrict__ sw,
                         const float* __restrict__ sc) {
    __shared__ __half sbuf[256 * NFEAT];
    int bx = blockIdx.x;
    int tid = threadIdx.x;
    int i = blockIdx.y * 256 + tid;
    float vals[NFEAT];

    if (bx < BATCH) {
        float xv = x[(size_t)bx * IN_F + i];
        // polynomial silu (MUFU-free)
        float tt = xv * xv;
        float P = fmaf(tt, fmaf(tt, fmaf(tt, -2.10813e-4f, 2.08333333e-3f),
                                -2.08333333e-2f), 0.25f);
        vals[0] = xv * fmaf(xv, P, 0.5f);
        // closed-form uniform cubic B-spline
        float u  = (xv + 1.0f) * 1.5f;
        int idx  = (int)floorf(u);
        idx = idx < 0 ? 0 : (idx > 2 ? 2 : idx);
        float t  = u - (float)idx;
        float t2 = t * t, t3 = t2 * t;
        float omt = 1.0f - t;
        const float c6 = 1.0f / 6.0f;
        float v0 = omt * omt * omt * c6;
        float v1 = (3.0f * t3 - 6.0f * t2 + 4.0f) * c6;
        float v2 = (-3.0f * t3 + 3.0f * t2 + 3.0f * t + 1.0f) * c6;
        float v3 = t3 * c6;
        vals[1] = (idx == 0) ? v0 : 0.0f;
        vals[2] = (idx == 0) ? v1 : ((idx == 1) ? v0 : 0.0f);
        vals[3] = (idx == 0) ? v2 : ((idx == 1) ? v1 : v0);
        vals[4] = (idx == 0) ? v3 : ((idx == 1) ? v2 : v1);
        vals[5] = (idx == 1) ? v3 : ((idx == 2) ? v2 : 0.0f);
        vals[6] = (idx == 2) ? v3 : 0.0f;
    } else {
        int o = bx - BATCH;
        size_t oi = (size_t)o * IN_F + i;
        float s = sc[oi];
        vals[0] = bw[oi];
        const float* swp = sw + oi * 6;
#pragma unroll
        for (int n = 0; n < 6; n++) vals[n + 1] = swp[n] * s;
    }

#pragma unroll
    for (int j = 0; j < NFEAT; j++)
        sbuf[tid * NFEAT + j] = __float2half_rn(vals[j]);
    __syncthreads();

    __half* gdst = (bx < BATCH) ? (g_A + (size_t)bx * KTOT)
                                : (g_W + (size_t)(bx - BATCH) * KTOT);
    float4* dst = (float4*)(gdst + (size_t)blockIdx.y * (256 * NFEAT));
    if (tid < 224) dst[tid] = ((const float4*)sbuf)[tid];
}

// ---------------------------------------------------------------------------
// Kernel 2: fp16 mma.sync m16n8k16 GEMM  C[b,o] = sum_k A[b][k] * W[o][k]
// OCCUPANCY EXPERIMENT: CTA 128x128, 3-stage ring = 108KB smem -> 2 CTAs/SM
// (16 warps/SM vs previous 8). 8 warps/CTA, warp tile 32x64.
// BK=64 halves, 144B row stride (conflict-free LDSM).
// ---------------------------------------------------------------------------
#define BM 128
#define BN 128
#define BK 64
#define NT (KTOT / BK)          // 112
#define ROWB 144                // bytes per smem row (128 data + 16 pad)
#define A_STG_B (BM * ROWB)     // 18432
#define B_STG_B (BN * ROWB)     // 18432
#define STG_B (A_STG_B + B_STG_B)   // 36864
#define NSTAGE 3
#define SMEM_TOTAL (NSTAGE * STG_B)   // 110592 -> 2 CTAs/SM

__device__ __forceinline__ void load_stage(uint32_t sb, int bm0, int bn0,
                                           int t, int stg, int tid) {
    uint32_t base = sb + stg * STG_B;
    int k0 = t * BK;
    // A: 128 rows x 8 chunks of 16B = 1024 chunks (4/thread)
#pragma unroll
    for (int r = 0; r < 4; r++) {
        int c = tid + r * 256;
        int row = c >> 3, ch = c & 7;
        CP_ASYNC16(base + (uint32_t)(row * ROWB + ch * 16),
                   g_A + (size_t)(bm0 + row) * KTOT + k0 + ch * 8);
    }
    // B: 128 rows x 8 chunks = 1024 chunks (4/thread)
    uint32_t bbase = base + A_STG_B;
#pragma unroll
    for (int r = 0; r < 4; r++) {
        int c = tid + r * 256;
        int row = c >> 3, ch = c & 7;
        CP_ASYNC16(bbase + (uint32_t)(row * ROWB + ch * 16),
                   g_W + (size_t)(bn0 + row) * KTOT + k0 + ch * 8);
    }
    CP_COMMIT();
}

__global__ __launch_bounds__(256, 2) void kan_gemm(float* __restrict__ C) {
    extern __shared__ char dsm[];
    uint32_t sb = smem_u32(dsm);
    const int tid = threadIdx.x;
    const int wid = tid >> 5, lane = tid & 31;
    const int q = lane >> 2, cl = lane & 3;
    const int bm0 = blockIdx.y * BM;   // y = bm (slow)
    const int bn0 = blockIdx.x * BN;   // x = bn (fast): consecutive CTAs share A
    const int m0 = (wid & 3) * 32;     // 4 warps in M
    const int n0 = (wid >> 2) * 64;    // 2 warps in N

    float d[2][8][4];
#pragma unroll
    for (int mb = 0; mb < 2; mb++)
#pragma unroll
        for (int nb = 0; nb < 8; nb++)
#pragma unroll
            for (int r = 0; r < 4; r++) d[mb][nb][r] = 0.0f;

    load_stage(sb, bm0, bn0, 0, 0, tid);
    load_stage(sb, bm0, bn0, 1, 1, tid);

    // LDSM lane addressing (same scheme as the verified R9 kernel):
    // A x4 tiles: (rowblk0,k0),(rowblk1,k0),(rowblk0,k8),(rowblk1,k8)
    // B x4 tiles: (nblk0,k0),(nblk0,k8),(nblk1,k0),(nblk1,k8)
    const int r8 = lane & 7, tq = lane >> 3;
    const uint32_t afoff =
        (uint32_t)((m0 + (tq & 1) * 8 + r8) * ROWB + (tq >> 1) * 16);
    const uint32_t bfoff =
        (uint32_t)(A_STG_B + (n0 + (tq >> 1) * 8 + r8) * ROWB + (tq & 1) * 16);

    for (int t = 0; t < NT; t++) {
        const int stg = t % NSTAGE;
        CP_WAIT(1);
        __syncthreads();
        if (t + 2 < NT) load_stage(sb, bm0, bn0, t + 2, (t + 2) % NSTAGE, tid);

        const uint32_t stbase = sb + stg * STG_B;
        const uint32_t abase = stbase + afoff;
        const uint32_t bbase = stbase + bfoff;

#pragma unroll
        for (int kk = 0; kk < 4; kk++) {
            const uint32_t ko = (uint32_t)(kk * 32);
            uint32_t a[2][4];     // a[mb]: 16 rows x k16 fragment
            LDSM_X4(a[0][0], a[0][1], a[0][2], a[0][3], abase + ko);
            LDSM_X4(a[1][0], a[1][1], a[1][2], a[1][3],
                    abase + (uint32_t)(16 * ROWB) + ko);
            uint32_t b[8][2];     // b[nb]: n8 x k16
#pragma unroll
            for (int n2 = 0; n2 < 4; n2++)
                LDSM_X4(b[2 * n2][0], b[2 * n2][1],
                        b[2 * n2 + 1][0], b[2 * n2 + 1][1],
                        bbase + (uint32_t)(n2 * 16 * ROWB) + ko);
#pragma unroll
            for (int mb = 0; mb < 2; mb++)
#pragma unroll
                for (int nb = 0; nb < 8; nb++)
                    MMA_F16(d[mb][nb], a[mb][0], a[mb][1], a[mb][2], a[mb][3],
                            b[nb][0], b[nb][1]);
        }
    }

    // epilogue
#pragma unroll
    for (int mb = 0; mb < 2; mb++) {
        int row0 = bm0 + m0 + mb * 16 + q;
#pragma unroll
        for (int nb = 0; nb < 8; nb++) {
            int col = bn0 + n0 + nb * 8 + 2 * cl;
            float2* p0 = (float2*)(C + (size_t)row0 * OUT_F + col);
            *p0 = make_float2(d[mb][nb][0], d[mb][nb][1]);
            float2* p1 = (float2*)(C + (size_t)(row0 + 8) * OUT_F + col);
            *p1 = make_float2(d[mb][nb][2], d[mb][nb][3]);
        }
    }
}

// ---------------------------------------------------------------------------
// Launch. Inputs: x, base_weight, spline_weight, spline_scaler, grid
// ---------------------------------------------------------------------------
extern "C" void kernel_launch(void* const* d_in, const int* in_sizes, int n_in,
                              void* d_out, int out_size) {
    (void)in_sizes; (void)n_in; (void)out_size;
    const float* x  = (const float*)d_in[0];
    const float* bw = (const float*)d_in[1];
    const float* sw = (const float*)d_in[2];
    const float* sc = (const float*)d_in[3];
    float* out = (float*)d_out;

    cudaFuncSetAttribute(kan_gemm, cudaFuncAttributeMaxDynamicSharedMemorySize,
                         SMEM_TOTAL);

    kan_prep<<<dim3(BATCH + OUT_F, IN_F / 256), 256>>>(x, bw, sw, sc);
    kan_gemm<<<dim3(OUT_F / BN, BATCH / BM), 256, SMEM_TOTAL>>>(out);
}

// round 14
// speedup vs baseline: 1.4324x; 1.0688x over previous
#include <cuda_runtime.h>
#include <cuda_fp16.h>
#include <cstdint>
#include <cstddef>

#define IN_F   1024
#define OUT_F  1024
#define BATCH  8192
#define NFEAT  7
#define KTOT   (IN_F * NFEAT)   // 7168

// ---------------------------------------------------------------------------
// Scratch: fp16 operands. g_A: [b][k] row-major. g_W: [o][k].
// ---------------------------------------------------------------------------
__device__ __align__(256) __half g_A[(size_t)BATCH * KTOT];
__device__ __align__(256) __half g_W[(size_t)OUT_F * KTOT];

// ---------------------------------------------------------------------------
// Helpers
// ---------------------------------------------------------------------------
__device__ __forceinline__ unsigned smem_u32(const void* p) {
    return (unsigned)__cvta_generic_to_shared(p);
}
#define CP_ASYNC16(dst_u32, src_ptr) \
    asm volatile("cp.async.cg.shared.global [%0], [%1], 16;\n" :: "r"(dst_u32), "l"(src_ptr))
#define CP_COMMIT() asm volatile("cp.async.commit_group;\n")
#define CP_WAIT(n)  asm volatile("cp.async.wait_group %0;\n" :: "n"(n))

#define LDSM_X4(r0, r1, r2, r3, addr) \
    asm volatile("ldmatrix.sync.aligned.m8n8.x4.shared.b16 {%0,%1,%2,%3}, [%4];" \
                 : "=r"(r0), "=r"(r1), "=r"(r2), "=r"(r3) : "r"(addr))

#define MMA_F16(d, a0, a1, a2, a3, b0, b1) \
    asm volatile( \
        "mma.sync.aligned.m16n8k16.row.col.f32.f16.f16.f32 " \
        "{%0,%1,%2,%3}, {%4,%5,%6,%7}, {%8,%9}, {%0,%1,%2,%3};" \
        : "+f"((d)[0]), "+f"((d)[1]), "+f"((d)[2]), "+f"((d)[3]) \
        : "r"(a0), "r"(a1), "r"(a2), "r"(a3), "r"(b0), "r"(b1))

// ---------------------------------------------------------------------------
// Kernel 1: combined prep (one launch, two independent grid partitions).
//   blockIdx.x <  BATCH : features for batch row bx -> g_A
//   blockIdx.x >= BATCH : combined weights for out row bx-BATCH -> g_W
// ---------------------------------------------------------------------------
__global__ void kan_prep(const float* __restrict__ x,
                         const float* __restrict__ bw,
                         const float* __restrict__ sw,
                         const float* __restrict__ sc) {
    __shared__ __half sbuf[256 * NFEAT];
    int bx = blockIdx.x;
    int tid = threadIdx.x;
    int i = blockIdx.y * 256 + tid;
    float vals[NFEAT];

    if (bx < BATCH) {
        float xv = x[(size_t)bx * IN_F + i];
        float tt = xv * xv;
        float P = fmaf(tt, fmaf(tt, fmaf(tt, -2.10813e-4f, 2.08333333e-3f),
                                -2.08333333e-2f), 0.25f);
        vals[0] = xv * fmaf(xv, P, 0.5f);
        float u  = (xv + 1.0f) * 1.5f;
        int idx  = (int)floorf(u);
        idx = idx < 0 ? 0 : (idx > 2 ? 2 : idx);
        float t  = u - (float)idx;
        float t2 = t * t, t3 = t2 * t;
        float omt = 1.0f - t;
        const float c6 = 1.0f / 6.0f;
        float v0 = omt * omt * omt * c6;
        float v1 = (3.0f * t3 - 6.0f * t2 + 4.0f) * c6;
        float v2 = (-3.0f * t3 + 3.0f * t2 + 3.0f * t + 1.0f) * c6;
        float v3 = t3 * c6;
        vals[1] = (idx == 0) ? v0 : 0.0f;
        vals[2] = (idx == 0) ? v1 : ((idx == 1) ? v0 : 0.0f);
        vals[3] = (idx == 0) ? v2 : ((idx == 1) ? v1 : v0);
        vals[4] = (idx == 0) ? v3 : ((idx == 1) ? v2 : v1);
        vals[5] = (idx == 1) ? v3 : ((idx == 2) ? v2 : 0.0f);
        vals[6] = (idx == 2) ? v3 : 0.0f;
    } else {
        int o = bx - BATCH;
        size_t oi = (size_t)o * IN_F + i;
        float s = sc[oi];
        vals[0] = bw[oi];
        const float* swp = sw + oi * 6;
#pragma unroll
        for (int n = 0; n < 6; n++) vals[n + 1] = swp[n] * s;
    }

#pragma unroll
    for (int j = 0; j < NFEAT; j++)
        sbuf[tid * NFEAT + j] = __float2half_rn(vals[j]);
    __syncthreads();

    __half* gdst = (bx < BATCH) ? (g_A + (size_t)bx * KTOT)
                                : (g_W + (size_t)(bx - BATCH) * KTOT);
    float4* dst = (float4*)(gdst + (size_t)blockIdx.y * (256 * NFEAT));
    if (tid < 224) dst[tid] = ((const float4*)sbuf)[tid];
}

// ---------------------------------------------------------------------------
// Kernel 2: fp16 mma.sync m16n8k16 GEMM  C[b,o] = sum_k A[b][k] * W[o][k]
// CTA 128x256, 512 threads = 16 warps (4 in M x 4 in N, warp tile 32x64),
// 1 CTA/SM. LDSM traffic 192B/MMA (vs 768 in R13) with 4 warps/SMSP to
// overlap LDSM under MMA. BK=64, 144B row stride (conflict-free LDSM),
// 3-stage cp.async ring.
// ---------------------------------------------------------------------------
#define BM 128
#define BN 256
#define BK 64
#define NT (KTOT / BK)          // 112
#define ROWB 144                // bytes per smem row (128 data + 16 pad)
#define A_STG_B (BM * ROWB)     // 18432
#define B_STG_B (BN * ROWB)     // 36864
#define STG_B (A_STG_B + B_STG_B)   // 55296
#define NSTAGE 3
#define SMEM_TOTAL (NSTAGE * STG_B)   // 165888
#define NTHREADS 512

__device__ __forceinline__ void load_stage(uint32_t sb, int bm0, int bn0,
                                           int t, int stg, int tid) {
    uint32_t base = sb + stg * STG_B;
    int k0 = t * BK;
    // A: 128 rows x 8 chunks of 16B = 1024 chunks (2/thread)
#pragma unroll
    for (int r = 0; r < 2; r++) {
        int c = tid + r * NTHREADS;
        int row = c >> 3, ch = c & 7;
        CP_ASYNC16(base + (uint32_t)(row * ROWB + ch * 16),
                   g_A + (size_t)(bm0 + row) * KTOT + k0 + ch * 8);
    }
    // B: 256 rows x 8 chunks = 2048 chunks (4/thread)
    uint32_t bbase = base + A_STG_B;
#pragma unroll
    for (int r = 0; r < 4; r++) {
        int c = tid + r * NTHREADS;
        int row = c >> 3, ch = c & 7;
        CP_ASYNC16(bbase + (uint32_t)(row * ROWB + ch * 16),
                   g_W + (size_t)(bn0 + row) * KTOT + k0 + ch * 8);
    }
    CP_COMMIT();
}

__global__ __launch_bounds__(NTHREADS, 1) void kan_gemm(float* __restrict__ C) {
    extern __shared__ char dsm[];
    uint32_t sb = smem_u32(dsm);
    const int tid = threadIdx.x;
    const int wid = tid >> 5, lane = tid & 31;
    const int q = lane >> 2, cl = lane & 3;
    const int bm0 = blockIdx.y * BM;   // y = bm (slow)
    const int bn0 = blockIdx.x * BN;   // x = bn (fast): consecutive CTAs share A
    const int m0 = (wid & 3) * 32;     // 4 warps in M
    const int n0 = (wid >> 2) * 64;    // 4 warps in N

    float d[2][8][4];
#pragma unroll
    for (int mb = 0; mb < 2; mb++)
#pragma unroll
        for (int nb = 0; nb < 8; nb++)
#pragma unroll
            for (int r = 0; r < 4; r++) d[mb][nb][r] = 0.0f;

    load_stage(sb, bm0, bn0, 0, 0, tid);
    load_stage(sb, bm0, bn0, 1, 1, tid);

    // LDSM lane addressing (verified R9/R13 scheme):
    // A x4 tiles: (rowblk0,k0),(rowblk1,k0),(rowblk0,k8),(rowblk1,k8)
    // B x4 tiles: (nblk0,k0),(nblk0,k8),(nblk1,k0),(nblk1,k8)
    const int r8 = lane & 7, tq = lane >> 3;
    const uint32_t afoff =
        (uint32_t)((m0 + (tq & 1) * 8 + r8) * ROWB + (tq >> 1) * 16);
    const uint32_t bfoff =
        (uint32_t)(A_STG_B + (n0 + (tq >> 1) * 8 + r8) * ROWB + (tq & 1) * 16);

    for (int t = 0; t < NT; t++) {
        const int stg = t % NSTAGE;
        CP_WAIT(1);
        __syncthreads();
        if (t + 2 < NT) load_stage(sb, bm0, bn0, t + 2, (t + 2) % NSTAGE, tid);

        const uint32_t stbase = sb + stg * STG_B;
        const uint32_t abase = stbase + afoff;
        const uint32_t bbase = stbase + bfoff;

#pragma unroll
        for (int kk = 0; kk < 4; kk++) {
            const uint32_t ko = (uint32_t)(kk * 32);
            uint32_t a[2][4];     // a[mb]: m16 x k16 fragment
            LDSM_X4(a[0][0], a[0][1], a[0][2], a[0][3], abase + ko);
            LDSM_X4(a[1][0], a[1][1], a[1][2], a[1][3],
                    abase + (uint32_t)(16 * ROWB) + ko);
            uint32_t b[8][2];     // b[nb]: n8 x k16
#pragma unroll
            for (int n2 = 0; n2 < 4; n2++)
                LDSM_X4(b[2 * n2][0], b[2 * n2][1],
                        b[2 * n2 + 1][0], b[2 * n2 + 1][1],
                        bbase + (uint32_t)(n2 * 16 * ROWB) + ko);
#pragma unroll
            for (int mb = 0; mb < 2; mb++)
#pragma unroll
                for (int nb = 0; nb < 8; nb++)
                    MMA_F16(d[mb][nb], a[mb][0], a[mb][1], a[mb][2], a[mb][3],
                            b[nb][0], b[nb][1]);
        }
    }

    // epilogue
#pragma unroll
    for (int mb = 0; mb < 2; mb++) {
        int row0 = bm0 + m0 + mb * 16 + q;
#pragma unroll
        for (int nb = 0; nb < 8; nb++) {
            int col = bn0 + n0 + nb * 8 + 2 * cl;
            float2* p0 = (float2*)(C + (size_t)row0 * OUT_F + col);
            *p0 = make_float2(d[mb][nb][0], d[mb][nb][1]);
            float2* p1 = (float2*)(C + (size_t)(row0 + 8) * OUT_F + col);
            *p1 = make_float2(d[mb][nb][2], d[mb][nb][3]);
        }
    }
}

// ---------------------------------------------------------------------------
// Launch. Inputs: x, base_weight, spline_weight, spline_scaler, grid
// ---------------------------------------------------------------------------
extern "C" void kernel_launch(void* const* d_in, const int* in_sizes, int n_in,
                              void* d_out, int out_size) {
    (void)in_sizes; (void)n_in; (void)out_size;
    const float* x  = (const float*)d_in[0];
    const float* bw = (const float*)d_in[1];
    const float* sw = (const float*)d_in[2];
    const float* sc = (const float*)d_in[3];
    float* out = (float*)d_out;

    cudaFuncSetAttribute(kan_gemm, cudaFuncAttributeMaxDynamicSharedMemorySize,
                         SMEM_TOTAL);

    kan_prep<<<dim3(BATCH + OUT_F, IN_F / 256), 256>>>(x, bw, sw, sc);
    kan_gemm<<<dim3(OUT_F / BN, BATCH / BM), NTHREADS, SMEM_TOTAL>>>(out);
}